// round 6
// baseline (speedup 1.0000x reference)
#include <cuda_runtime.h>
#include <cstdint>
#include <math_constants.h>

#define N_NODES 100000
#define N_EDGES 800000
#define DIM 64
#define HEADS 4
#define NCHUNK 98   // ceil(N_NODES/1024)

// ---------------- scratch (static __device__, no allocations) ----------------
__device__ float g_q[N_NODES * DIM];
__device__ float g_k[N_NODES * DIM];
__device__ float g_v[N_NODES * DIM];
__device__ float g_csr_att[N_EDGES * HEADS];     // raw logits -> exp(logit-m), CSR order
__device__ float g_dinv[N_NODES * HEADS];        // 1/(denom+eps)
__device__ int   g_src[N_EDGES];
__device__ int   g_dst[N_EDGES];
__device__ int   g_csr_src[N_EDGES];
__device__ int   g_csr_eid[N_EDGES];
__device__ int   g_deg[N_NODES];
__device__ int   g_rowptr[N_NODES + 1];
__device__ int   g_cursor[N_NODES];
__device__ int   g_chunksum[NCHUNK];
__device__ int   g_chunkoff[NCHUNK];
__device__ float g_zA[N_NODES * DIM];
__device__ float g_zB[N_NODES * DIM];
__device__ int   g_is64;

// ---------------- kernels ----------------

// detect whether edge_index is really int64 or silently int32 (JAX x64 off)
__global__ void k_detect(const long long* __restrict__ ei) {
    int ok = 1;
    for (int i = 0; i < 64; i++) {
        long long v = ei[i];
        if (v < 0 || v >= N_NODES) ok = 0;
    }
    g_is64 = ok;
}

__global__ void k_zero() {
    int i = blockIdx.x * blockDim.x + threadIdx.x;
    if (i < N_NODES) g_deg[i] = 0;
}

__global__ void k_prep(const long long* __restrict__ ei) {
    int i = blockIdx.x * blockDim.x + threadIdx.x;
    if (i >= N_EDGES) return;
    int s, d;
    if (g_is64) {
        s = (int)ei[i];
        d = (int)ei[N_EDGES + i];
    } else {
        const int* e32 = (const int*)ei;
        s = e32[i];
        d = e32[N_EDGES + i];
    }
    g_src[i] = s;
    g_dst[i] = d;
    atomicAdd(&g_deg[d], 1);
}

__global__ void k_chunksum() {
    __shared__ int sh[256];
    int b = blockIdx.x, t = threadIdx.x;
    int base = b * 1024;
    int sum = 0;
    for (int k = 0; k < 4; k++) {
        int i = base + k * 256 + t;
        if (i < N_NODES) sum += g_deg[i];
    }
    sh[t] = sum;
    __syncthreads();
    for (int off = 128; off; off >>= 1) {
        if (t < off) sh[t] += sh[t + off];
        __syncthreads();
    }
    if (t == 0) g_chunksum[b] = sh[0];
}

__global__ void k_scanmid() {
    int run = 0;
    for (int c = 0; c < NCHUNK; c++) {
        g_chunkoff[c] = run;
        run += g_chunksum[c];
    }
    g_rowptr[N_NODES] = run;
}

__global__ void k_scanchunk() {
    __shared__ int s[1024];
    int b = blockIdx.x, t = threadIdx.x;
    int i = b * 1024 + t;
    int v = (i < N_NODES) ? g_deg[i] : 0;
    s[t] = v;
    __syncthreads();
    for (int off = 1; off < 1024; off <<= 1) {
        int add = (t >= off) ? s[t - off] : 0;
        __syncthreads();
        s[t] += add;
        __syncthreads();
    }
    if (i < N_NODES) {
        int ex = g_chunkoff[b] + s[t] - v;   // exclusive prefix
        g_rowptr[i] = ex;
        g_cursor[i] = ex;
    }
}

__global__ void k_scatter() {
    int e = blockIdx.x * blockDim.x + threadIdx.x;
    if (e >= N_EDGES) return;
    int dst = g_dst[e];
    int p = atomicAdd(&g_cursor[dst], 1);
    g_csr_src[p] = g_src[e];
    g_csr_eid[p] = e;
}

// q/k/v projections: 32 rows per block, register-blocked (8 rows/thread-group)
__global__ void k_qkv(const float* __restrict__ x, const float* __restrict__ Wq,
                      const float* __restrict__ Wk, const float* __restrict__ Wv) {
    __shared__ float xs[32][64];
    int n0 = blockIdx.x * 32;
    int t = threadIdx.x;
    for (int k = 0; k < 8; k++) {
        int L = k * 256 + t;
        xs[L >> 6][L & 63] = x[n0 * 64 + L];
    }
    __syncthreads();
    int col = t & 63, rg = t >> 6;
    float aq[8] = {0}, ak[8] = {0}, av[8] = {0};
#pragma unroll 4
    for (int j = 0; j < 64; j++) {
        float wq = Wq[j * 64 + col];
        float wk = Wk[j * 64 + col];
        float wv = Wv[j * 64 + col];
#pragma unroll
        for (int r = 0; r < 8; r++) {
            float xv = xs[rg * 8 + r][j];
            aq[r] += xv * wq;
            ak[r] += xv * wk;
            av[r] += xv * wv;
        }
    }
#pragma unroll
    for (int r = 0; r < 8; r++) {
        int n = n0 + rg * 8 + r;
        g_q[n * 64 + col] = aq[r];
        g_k[n * 64 + col] = ak[r];
        g_v[n * 64 + col] = av[r];
    }
}

// Fused per-node attention, edge-parallel layout.
// Warp per node. Phase 1: lanes cooperatively build p[h][j] (j=0..63) into
// shared (p[n,h,j] = sum_d We[j, h*16+d] * q[n,h,d]). Phase 2: lane
// (h=lane>>3, g=lane&7) computes FULL logits for edges beg+g, beg+g+8, ...
// of head h (no per-edge shuffles). Phase 3: 8-wide parallel segment softmax
// with one butterfly max + one butterfly sum per node.
__global__ void k_node(const float* __restrict__ ea, const float* __restrict__ We) {
    __shared__ float ps[8][256];   // per-warp p, [h*64 + j]
    int w = threadIdx.x >> 5;
    int node = blockIdx.x * 8 + w;
    if (node >= N_NODES) return;
    int lane = threadIdx.x & 31, h = lane >> 3, g = lane & 7;

    // q for this lane's head (16 floats, register resident)
    const float4* q4 = (const float4*)(g_q + node * 64 + h * 16);
    float4 qa = q4[0], qb = q4[1], qc = q4[2], qd = q4[3];

    // p[h][g*8+jj] = We[g*8+jj, h*16 + :] . q[node, h, :]
#pragma unroll
    for (int jj = 0; jj < 8; jj++) {
        const float4* w4 = (const float4*)(We + (g * 8 + jj) * 64 + h * 16);
        float4 w0 = w4[0], w1 = w4[1], w2 = w4[2], w3 = w4[3];
        float pv = w0.x * qa.x + w0.y * qa.y + w0.z * qa.z + w0.w * qa.w
                 + w1.x * qb.x + w1.y * qb.y + w1.z * qb.z + w1.w * qb.w
                 + w2.x * qc.x + w2.y * qc.y + w2.z * qc.z + w2.w * qc.w
                 + w3.x * qd.x + w3.y * qd.y + w3.z * qd.z + w3.w * qd.w;
        ps[w][h * 64 + g * 8 + jj] = pv;
    }
    __syncwarp();

    int beg = g_rowptr[node], end = g_rowptr[node + 1];
    const float* pr = &ps[w][h * 64];
    float mloc = -CUDART_INF_F;

    for (int base = beg; base < end; base += 8) {
        int i = base + g;
        float logit = -CUDART_INF_F;
        if (i < end) {
            int src = g_csr_src[i];
            int eid = g_csr_eid[i];
            const float4* e4 = (const float4*)(ea + (size_t)eid * 64);
            float acc = 0.0f;
#pragma unroll
            for (int c = 0; c < 16; c++) {
                float4 ev = e4[c];
                acc += ev.x * pr[c * 4] + ev.y * pr[c * 4 + 1]
                     + ev.z * pr[c * 4 + 2] + ev.w * pr[c * 4 + 3];
            }
            const float4* k4 = (const float4*)(g_k + src * 64 + h * 16);
            float4 k0 = k4[0], k1 = k4[1], k2 = k4[2], k3 = k4[3];
            acc += k0.x * qa.x + k0.y * qa.y + k0.z * qa.z + k0.w * qa.w
                 + k1.x * qb.x + k1.y * qb.y + k1.z * qb.z + k1.w * qb.w
                 + k2.x * qc.x + k2.y * qc.y + k2.z * qc.z + k2.w * qc.w
                 + k3.x * qd.x + k3.y * qd.y + k3.z * qd.z + k3.w * qd.w;
            logit = acc * 0.25f;   // 1/sqrt(16)
            g_csr_att[i * 4 + h] = logit;
        }
        mloc = fmaxf(mloc, logit);
    }
    // one butterfly max within the 8-lane head group
    mloc = fmaxf(mloc, __shfl_xor_sync(0xFFFFFFFFu, mloc, 1));
    mloc = fmaxf(mloc, __shfl_xor_sync(0xFFFFFFFFu, mloc, 2));
    mloc = fmaxf(mloc, __shfl_xor_sync(0xFFFFFFFFu, mloc, 4));
    __syncwarp();   // make phase-2 logit stores visible warp-wide

    float sum = 0.0f;
    for (int i = beg + g; i < end; i += 8) {
        float a = __expf(g_csr_att[i * 4 + h] - mloc);
        g_csr_att[i * 4 + h] = a;   // unnormalized; k_prop applies g_dinv
        sum += a;
    }
    sum += __shfl_xor_sync(0xFFFFFFFFu, sum, 1);
    sum += __shfl_xor_sync(0xFFFFFFFFu, sum, 2);
    sum += __shfl_xor_sync(0xFFFFFFFFu, sum, 4);
    if (g == 0) g_dinv[node * 4 + h] = 1.0f / (sum + 1e-16f);
}

// propagation: warp per node, pure gather. Normalization folded in via g_dinv.
// iter==7 fuses the final relu + residual and writes to out.
__global__ void k_prop(int iter, const float* __restrict__ x, float* __restrict__ out) {
    int gid = blockIdx.x * blockDim.x + threadIdx.x;
    int node = gid >> 5;
    if (node >= N_NODES) return;
    int lane = gid & 31;
    const float* zold = (iter == 0) ? g_v : ((iter & 1) ? g_zA : g_zB);
    float* znew = (iter & 1) ? g_zB : g_zA;
    int beg = g_rowptr[node], end = g_rowptr[node + 1];
    int h = lane >> 3;
    float inv = g_dinv[node * 4 + h];
    float ax = 0.0f, ay = 0.0f;
    for (int i = beg; i < end; i++) {
        int s = g_csr_src[i];
        float a = g_csr_att[i * 4 + h];
        float2 z = *(const float2*)(zold + s * 64 + lane * 2);
        ax += a * z.x;
        ay += a * z.y;
    }
    float2 vv = *(const float2*)(g_v + node * 64 + lane * 2);
    float ox = 0.1f * vv.x + 0.9f * (ax * inv);
    float oy = 0.1f * vv.y + 0.9f * (ay * inv);
    if (iter == 7) {
        float2 xv = *(const float2*)(x + node * 64 + lane * 2);
        float2 o;
        o.x = xv.x + fmaxf(ox, 0.0f);
        o.y = xv.y + fmaxf(oy, 0.0f);
        *(float2*)(out + node * 64 + lane * 2) = o;
    } else {
        float2 o; o.x = ox; o.y = oy;
        *(float2*)(znew + node * 64 + lane * 2) = o;
    }
}

// ---------------- launch ----------------
extern "C" void kernel_launch(void* const* d_in, const int* in_sizes, int n_in,
                              void* d_out, int out_size) {
    const float*     x  = (const float*)d_in[0];
    const long long* ei = (const long long*)d_in[1];
    const float*     ea = (const float*)d_in[2];
    const float*     Wq = (const float*)d_in[3];
    const float*     Wk = (const float*)d_in[4];
    const float*     Wv = (const float*)d_in[5];
    const float*     We = (const float*)d_in[6];
    float* out = (float*)d_out;

    k_detect<<<1, 1>>>(ei);
    k_zero<<<(N_NODES + 255) / 256, 256>>>();
    k_prep<<<(N_EDGES + 255) / 256, 256>>>(ei);
    k_chunksum<<<NCHUNK, 256>>>();
    k_scanmid<<<1, 1>>>();
    k_scanchunk<<<NCHUNK, 1024>>>();
    k_scatter<<<(N_EDGES + 255) / 256, 256>>>();
    k_qkv<<<N_NODES / 32, 256>>>(x, Wq, Wk, Wv);
    k_node<<<(N_NODES + 7) / 8, 256>>>(ea, We);
    for (int it = 0; it < 8; it++)
        k_prop<<<(N_NODES * 32 + 255) / 256, 256>>>(it, x, out);
}

// round 8
// speedup vs baseline: 1.5113x; 1.5113x over previous
#include <cuda_runtime.h>
#include <cstdint>
#include <math_constants.h>

#define N_NODES 100000
#define N_EDGES 800000
#define DIM 64
#define HEADS 4
#define NCHUNK 98   // ceil(N_NODES/1024)

// ---------------- scratch (static __device__, no allocations) ----------------
__device__ float g_q[N_NODES * DIM];
__device__ float g_k[N_NODES * DIM];
__device__ float g_v[N_NODES * DIM];
__device__ float g_p[N_NODES * DIM * HEADS];     // [n][h*64+j]
__device__ float g_att[N_EDGES * HEADS];         // CSR order: logits -> exp(logit-m)
__device__ float g_dinv[N_NODES * HEADS];        // 1/(denom+eps)
__device__ int   g_src[N_EDGES];
__device__ int   g_dst[N_EDGES];
__device__ int   g_csr_src[N_EDGES];
__device__ int   g_csr_dst[N_EDGES];
__device__ int   g_csr_eid[N_EDGES];
__device__ int   g_deg[N_NODES];
__device__ int   g_rowptr[N_NODES + 1];
__device__ int   g_cursor[N_NODES];
__device__ int   g_chunksum[NCHUNK];
__device__ int   g_chunkoff[NCHUNK];
__device__ unsigned g_menc[N_NODES * HEADS];
__device__ float g_denom[N_NODES * HEADS];
__device__ float g_zA[N_NODES * DIM];
__device__ float g_zB[N_NODES * DIM];
__device__ int   g_is64;

// ordered-uint encoding of float for atomicMax
__device__ __forceinline__ unsigned fenc(float f) {
    unsigned u = __float_as_uint(f);
    return (u & 0x80000000u) ? ~u : (u | 0x80000000u);
}
__device__ __forceinline__ float fdec(unsigned u) {
    unsigned b = (u & 0x80000000u) ? (u & 0x7FFFFFFFu) : ~u;
    return __uint_as_float(b);
}

// ---------------- kernels ----------------

// detect whether edge_index is really int64 or silently int32 (JAX x64 off)
__global__ void k_detect(const long long* __restrict__ ei) {
    int ok = 1;
    for (int i = 0; i < 64; i++) {
        long long v = ei[i];
        if (v < 0 || v >= N_NODES) ok = 0;
    }
    g_is64 = ok;
}

__global__ void k_zero() {
    int i = blockIdx.x * blockDim.x + threadIdx.x;
    if (i < N_NODES * HEADS) { g_menc[i] = 0u; g_denom[i] = 0.0f; }
    if (i < N_NODES) g_deg[i] = 0;
}

__global__ void k_prep(const long long* __restrict__ ei) {
    int i = blockIdx.x * blockDim.x + threadIdx.x;
    if (i >= N_EDGES) return;
    int s, d;
    if (g_is64) {
        s = (int)ei[i];
        d = (int)ei[N_EDGES + i];
    } else {
        const int* e32 = (const int*)ei;
        s = e32[i];
        d = e32[N_EDGES + i];
    }
    g_src[i] = s;
    g_dst[i] = d;
    atomicAdd(&g_deg[d], 1);
}

// q/k/v projections: 32 rows per block, register-blocked (8 rows/thread-group)
__global__ void k_qkv(const float* __restrict__ x, const float* __restrict__ Wq,
                      const float* __restrict__ Wk, const float* __restrict__ Wv) {
    __shared__ float xs[32][64];
    int n0 = blockIdx.x * 32;
    int t = threadIdx.x;
    for (int k = 0; k < 8; k++) {
        int L = k * 256 + t;
        xs[L >> 6][L & 63] = x[n0 * 64 + L];
    }
    __syncthreads();
    int col = t & 63, rg = t >> 6;
    float aq[8] = {0}, ak[8] = {0}, av[8] = {0};
#pragma unroll 4
    for (int j = 0; j < 64; j++) {
        float wq = Wq[j * 64 + col];
        float wk = Wk[j * 64 + col];
        float wv = Wv[j * 64 + col];
#pragma unroll
        for (int r = 0; r < 8; r++) {
            float xv = xs[rg * 8 + r][j];
            aq[r] += xv * wq;
            ak[r] += xv * wk;
            av[r] += xv * wv;
        }
    }
#pragma unroll
    for (int r = 0; r < 8; r++) {
        int n = n0 + rg * 8 + r;
        g_q[n * 64 + col] = aq[r];
        g_k[n * 64 + col] = ak[r];
        g_v[n * 64 + col] = av[r];
    }
}

// p[n,h,j] = sum_d We[j, h*16+d] * q[n, h*16+d]   (16 nodes per block)
__global__ void k_p(const float* __restrict__ We) {
    __shared__ float qs[16][64];
    int n0 = blockIdx.x * 16, t = threadIdx.x;
    for (int k = 0; k < 4; k++) {
        int L = k * 256 + t;
        qs[L >> 6][L & 63] = g_q[n0 * 64 + L];
    }
    __syncthreads();
    int h = t >> 6, j = t & 63;
    const float4* wp = (const float4*)(We + j * 64 + h * 16);
    float4 w0 = wp[0], w1 = wp[1], w2 = wp[2], w3 = wp[3];
#pragma unroll 4
    for (int nl = 0; nl < 16; nl++) {
        const float* qr = &qs[nl][h * 16];
        float acc = w0.x * qr[0] + w0.y * qr[1] + w0.z * qr[2] + w0.w * qr[3]
                  + w1.x * qr[4] + w1.y * qr[5] + w1.z * qr[6] + w1.w * qr[7]
                  + w2.x * qr[8] + w2.y * qr[9] + w2.z * qr[10] + w2.w * qr[11]
                  + w3.x * qr[12] + w3.y * qr[13] + w3.z * qr[14] + w3.w * qr[15];
        g_p[(n0 + nl) * 256 + h * 64 + j] = acc;
    }
}

__global__ void k_chunksum() {
    __shared__ int sh[256];
    int b = blockIdx.x, t = threadIdx.x;
    int base = b * 1024;
    int sum = 0;
    for (int k = 0; k < 4; k++) {
        int i = base + k * 256 + t;
        if (i < N_NODES) sum += g_deg[i];
    }
    sh[t] = sum;
    __syncthreads();
    for (int off = 128; off; off >>= 1) {
        if (t < off) sh[t] += sh[t + off];
        __syncthreads();
    }
    if (t == 0) g_chunksum[b] = sh[0];
}

__global__ void k_scanmid() {
    int run = 0;
    for (int c = 0; c < NCHUNK; c++) {
        g_chunkoff[c] = run;
        run += g_chunksum[c];
    }
    g_rowptr[N_NODES] = run;
}

__global__ void k_scanchunk() {
    __shared__ int s[1024];
    int b = blockIdx.x, t = threadIdx.x;
    int i = b * 1024 + t;
    int v = (i < N_NODES) ? g_deg[i] : 0;
    s[t] = v;
    __syncthreads();
    for (int off = 1; off < 1024; off <<= 1) {
        int add = (t >= off) ? s[t - off] : 0;
        __syncthreads();
        s[t] += add;
        __syncthreads();
    }
    if (i < N_NODES) {
        int ex = g_chunkoff[b] + s[t] - v;   // exclusive prefix
        g_rowptr[i] = ex;
        g_cursor[i] = ex;
    }
}

__global__ void k_scatter() {
    int e = blockIdx.x * blockDim.x + threadIdx.x;
    if (e >= N_EDGES) return;
    int dst = g_dst[e];
    int p = atomicAdd(&g_cursor[dst], 1);
    g_csr_src[p] = g_src[e];
    g_csr_dst[p] = dst;
    g_csr_eid[p] = e;
}

// logits in CSR order: 64 CSR slots/block, thread = (el = t>>2, h = t&3).
// Consecutive CSR slots share dst -> p[dst] row (1KB) hits L1/L2 instead of
// being re-gathered from DRAM per edge (R1 did 820MB; this does ~102MB).
#define EA_STRIDE 68
__global__ void k_logits(const float* __restrict__ ea) {
    __shared__ float eas[64 * EA_STRIDE];
    __shared__ int ss[64], sd[64], se[64];
    int e0 = blockIdx.x * 64, t = threadIdx.x;
    if (t < 64) {
        ss[t] = g_csr_src[e0 + t];
        sd[t] = g_csr_dst[e0 + t];
        se[t] = g_csr_eid[e0 + t];
    }
    __syncthreads();
    // stage ea rows (gathered by eid): 4 threads per row, 16 floats each
    {
        int row = t >> 2, part = t & 3;
        const float4* src4 = (const float4*)(ea + (size_t)se[row] * 64 + part * 16);
        float* dstp = &eas[row * EA_STRIDE + part * 16];
#pragma unroll
        for (int k = 0; k < 4; k++) {
            float4 v = src4[k];
            dstp[k * 4 + 0] = v.x;
            dstp[k * 4 + 1] = v.y;
            dstp[k * 4 + 2] = v.z;
            dstp[k * 4 + 3] = v.w;
        }
    }
    __syncthreads();
    int el = t >> 2, h = t & 3;
    int dst = sd[el], src = ss[el];
    const float4* qp = (const float4*)(g_q + dst * 64 + h * 16);
    const float4* kp = (const float4*)(g_k + src * 64 + h * 16);
    float acc = 0.0f;
#pragma unroll
    for (int c = 0; c < 4; c++) {
        float4 qv = qp[c], kv = kp[c];
        acc += qv.x * kv.x + qv.y * kv.y + qv.z * kv.z + qv.w * kv.w;
    }
    const float4* pp = (const float4*)(g_p + dst * 256 + h * 64);
    const float4* er = (const float4*)&eas[el * EA_STRIDE];
#pragma unroll
    for (int j = 0; j < 16; j++) {
        float4 pv = pp[j];
        float4 ev = er[j];
        acc += ev.x * pv.x + ev.y * pv.y + ev.z * pv.z + ev.w * pv.w;
    }
    float logit = acc * 0.25f;   // 1/sqrt(16)
    g_att[e0 * 4 + t] = logit;   // (e0+el)*4 + h == e0*4 + t  (coalesced)
    atomicMax(&g_menc[dst * 4 + h], fenc(logit));
}

__global__ void k_exp() {
    int i = blockIdx.x * blockDim.x + threadIdx.x;
    if (i >= N_EDGES * HEADS) return;
    int e = i >> 2, h = i & 3;
    int dst = g_csr_dst[e];
    float m = fdec(g_menc[dst * 4 + h]);
    float ex = __expf(g_att[i] - m);
    g_att[i] = ex;               // unnormalized; k_prop applies g_dinv
    atomicAdd(&g_denom[dst * 4 + h], ex);
}

__global__ void k_dinv() {
    int i = blockIdx.x * blockDim.x + threadIdx.x;
    if (i < N_NODES * HEADS) g_dinv[i] = 1.0f / (g_denom[i] + 1e-16f);
}

// propagation: warp per node, pure gather. Normalization folded in via g_dinv.
// iter==7 fuses the final relu + residual and writes to out.
__global__ void k_prop(int iter, const float* __restrict__ x, float* __restrict__ out) {
    int gid = blockIdx.x * blockDim.x + threadIdx.x;
    int node = gid >> 5;
    if (node >= N_NODES) return;
    int lane = gid & 31;
    const float* zold = (iter == 0) ? g_v : ((iter & 1) ? g_zA : g_zB);
    float* znew = (iter & 1) ? g_zB : g_zA;
    int beg = g_rowptr[node], end = g_rowptr[node + 1];
    int h = lane >> 3;
    float inv = g_dinv[node * 4 + h];
    float ax = 0.0f, ay = 0.0f;
    for (int i = beg; i < end; i++) {
        int s = g_csr_src[i];
        float a = g_att[i * 4 + h];
        float2 z = *(const float2*)(zold + s * 64 + lane * 2);
        ax += a * z.x;
        ay += a * z.y;
    }
    float2 vv = *(const float2*)(g_v + node * 64 + lane * 2);
    float ox = 0.1f * vv.x + 0.9f * (ax * inv);
    float oy = 0.1f * vv.y + 0.9f * (ay * inv);
    if (iter == 7) {
        float2 xv = *(const float2*)(x + node * 64 + lane * 2);
        float2 o;
        o.x = xv.x + fmaxf(ox, 0.0f);
        o.y = xv.y + fmaxf(oy, 0.0f);
        *(float2*)(out + node * 64 + lane * 2) = o;
    } else {
        float2 o; o.x = ox; o.y = oy;
        *(float2*)(znew + node * 64 + lane * 2) = o;
    }
}

// ---------------- launch ----------------
// NOTE: k_qkv / k_p placed at launch positions 4/5 so the ncu slot (-s 5 -c 1,
// which has been landing on the 4th-6th launch) captures a real kernel.
extern "C" void kernel_launch(void* const* d_in, const int* in_sizes, int n_in,
                              void* d_out, int out_size) {
    const float*     x  = (const float*)d_in[0];
    const long long* ei = (const long long*)d_in[1];
    const float*     ea = (const float*)d_in[2];
    const float*     Wq = (const float*)d_in[3];
    const float*     Wk = (const float*)d_in[4];
    const float*     Wv = (const float*)d_in[5];
    const float*     We = (const float*)d_in[6];
    float* out = (float*)d_out;

    k_detect<<<1, 1>>>(ei);                                   // 1
    k_zero<<<(N_NODES * HEADS + 255) / 256, 256>>>();         // 2
    k_prep<<<(N_EDGES + 255) / 256, 256>>>(ei);               // 3
    k_qkv<<<N_NODES / 32, 256>>>(x, Wq, Wk, Wv);              // 4  <- profile slot?
    k_p<<<N_NODES / 16, 256>>>(We);                           // 5  <- profile slot?
    k_chunksum<<<NCHUNK, 256>>>();                            // 6
    k_scanmid<<<1, 1>>>();                                    // 7
    k_scanchunk<<<NCHUNK, 1024>>>();                          // 8
    k_scatter<<<(N_EDGES + 255) / 256, 256>>>();              // 9
    k_logits<<<N_EDGES / 64, 256>>>(ea);                      // 10
    k_exp<<<(N_EDGES * HEADS + 255) / 256, 256>>>();          // 11
    k_dinv<<<(N_NODES * HEADS + 255) / 256, 256>>>();         // 12
    for (int it = 0; it < 8; it++)
        k_prop<<<(N_NODES * 32 + 255) / 256, 256>>>(it, x, out);  // 13-20
}

// round 9
// speedup vs baseline: 1.5203x; 1.0059x over previous
#include <cuda_runtime.h>
#include <cstdint>
#include <math_constants.h>

#define N_NODES 100000
#define N_EDGES 800000
#define DIM 64
#define HEADS 4
#define NCHUNK 98   // ceil(N_NODES/1024)

// ---------------- scratch (static __device__, no allocations) ----------------
__device__ float g_q[N_NODES * DIM];
__device__ float g_k[N_NODES * DIM];
__device__ float g_v[N_NODES * DIM];
__device__ float g_p[N_NODES * DIM * HEADS];     // [n][h*64+j]
__device__ float g_att[N_EDGES * HEADS];         // CSR order: logits -> exp(logit-m)
__device__ float g_dinv[N_NODES * HEADS];        // 1/(denom+eps)
__device__ int   g_src[N_EDGES];
__device__ int   g_dst[N_EDGES];
__device__ int   g_csr_src[N_EDGES];
__device__ int   g_csr_dst[N_EDGES];
__device__ int   g_csr_eid[N_EDGES];
__device__ int   g_deg[N_NODES];
__device__ int   g_rowptr[N_NODES + 1];
__device__ int   g_cursor[N_NODES];
__device__ int   g_chunksum[NCHUNK];
__device__ int   g_chunkoff[NCHUNK];
__device__ unsigned g_menc[N_NODES * HEADS];
__device__ float g_denom[N_NODES * HEADS];
__device__ float g_zA[N_NODES * DIM];
__device__ float g_zB[N_NODES * DIM];
__device__ int   g_is64;

// ordered-uint encoding of float for atomicMax
__device__ __forceinline__ unsigned fenc(float f) {
    unsigned u = __float_as_uint(f);
    return (u & 0x80000000u) ? ~u : (u | 0x80000000u);
}
__device__ __forceinline__ float fdec(unsigned u) {
    unsigned b = (u & 0x80000000u) ? (u & 0x7FFFFFFFu) : ~u;
    return __uint_as_float(b);
}

// packed f32x2 helpers (FFMA2 is only reachable via PTX fma.rn.f32x2)
__device__ __forceinline__ unsigned long long pk2(float a, float b) {
    unsigned long long r;
    asm("mov.b64 %0, {%1, %2};" : "=l"(r) : "f"(a), "f"(b));
    return r;
}
__device__ __forceinline__ unsigned long long ffma2(unsigned long long a,
                                                    unsigned long long b,
                                                    unsigned long long c) {
    unsigned long long d;
    asm("fma.rn.f32x2 %0, %1, %2, %3;" : "=l"(d) : "l"(a), "l"(b), "l"(c));
    return d;
}
__device__ __forceinline__ void upk2(unsigned long long v, float& lo, float& hi) {
    asm("mov.b64 {%0, %1}, %2;" : "=f"(lo), "=f"(hi) : "l"(v));
}

// ---------------- kernels ----------------

// detect whether edge_index is really int64 or silently int32 (JAX x64 off)
__global__ void k_detect(const long long* __restrict__ ei) {
    int ok = 1;
    for (int i = 0; i < 64; i++) {
        long long v = ei[i];
        if (v < 0 || v >= N_NODES) ok = 0;
    }
    g_is64 = ok;
}

__global__ void k_zero() {
    int i = blockIdx.x * blockDim.x + threadIdx.x;
    if (i < N_NODES * HEADS) { g_menc[i] = 0u; g_denom[i] = 0.0f; }
    if (i < N_NODES) g_deg[i] = 0;
}

__global__ void k_prep(const long long* __restrict__ ei) {
    int i = blockIdx.x * blockDim.x + threadIdx.x;
    if (i >= N_EDGES) return;
    int s, d;
    if (g_is64) {
        s = (int)ei[i];
        d = (int)ei[N_EDGES + i];
    } else {
        const int* e32 = (const int*)ei;
        s = e32[i];
        d = e32[N_EDGES + i];
    }
    g_src[i] = s;
    g_dst[i] = d;
    atomicAdd(&g_deg[d], 1);
}

// q/k/v projections with packed f32x2 FMA.
// 32 rows/block. x staged TRANSPOSED in shared: xs[dim][row] (stride 34 keeps
// 8B alignment for 64-bit row-pair loads; all lanes of a warp read the same
// address -> broadcast). Thread = (col = t&63, row-group rg = t>>6, 8 rows).
// Accumulators pack row pairs {2r, 2r+1} -> 12 FFMA2 + 4 LDS.64 per j-step
// instead of 24 FFMA + 8 LDS.
__global__ void k_qkv(const float* __restrict__ x, const float* __restrict__ Wq,
                      const float* __restrict__ Wk, const float* __restrict__ Wv) {
    __shared__ float xs[64][34];
    int n0 = blockIdx.x * 32;
    int t = threadIdx.x;
    for (int kk = 0; kk < 8; kk++) {
        int L = kk * 256 + t;            // L = row*64 + dim
        xs[L & 63][L >> 6] = x[n0 * 64 + L];
    }
    __syncthreads();
    int col = t & 63, rg = t >> 6;
    unsigned long long aq[4], ak[4], av[4];
#pragma unroll
    for (int rp = 0; rp < 4; rp++) { aq[rp] = 0ull; ak[rp] = 0ull; av[rp] = 0ull; }
#pragma unroll 4
    for (int j = 0; j < 64; j++) {
        unsigned long long wq2 = pk2(Wq[j * 64 + col], Wq[j * 64 + col]);
        unsigned long long wk2 = pk2(Wk[j * 64 + col], Wk[j * 64 + col]);
        unsigned long long wv2 = pk2(Wv[j * 64 + col], Wv[j * 64 + col]);
        const unsigned long long* xr =
            (const unsigned long long*)&xs[j][rg * 8];   // 8B-aligned (stride 34)
#pragma unroll
        for (int rp = 0; rp < 4; rp++) {
            unsigned long long xv2 = xr[rp];             // rows {rg*8+2rp, +1}
            aq[rp] = ffma2(xv2, wq2, aq[rp]);
            ak[rp] = ffma2(xv2, wk2, ak[rp]);
            av[rp] = ffma2(xv2, wv2, av[rp]);
        }
    }
#pragma unroll
    for (int rp = 0; rp < 4; rp++) {
        int n = n0 + rg * 8 + rp * 2;
        float lo, hi;
        upk2(aq[rp], lo, hi);
        g_q[n * 64 + col] = lo; g_q[(n + 1) * 64 + col] = hi;
        upk2(ak[rp], lo, hi);
        g_k[n * 64 + col] = lo; g_k[(n + 1) * 64 + col] = hi;
        upk2(av[rp], lo, hi);
        g_v[n * 64 + col] = lo; g_v[(n + 1) * 64 + col] = hi;
    }
}

// p[n,h,j] = sum_d We[j, h*16+d] * q[n, h*16+d]   (16 nodes per block)
__global__ void k_p(const float* __restrict__ We) {
    __shared__ float qs[16][64];
    int n0 = blockIdx.x * 16, t = threadIdx.x;
    for (int k = 0; k < 4; k++) {
        int L = k * 256 + t;
        qs[L >> 6][L & 63] = g_q[n0 * 64 + L];
    }
    __syncthreads();
    int h = t >> 6, j = t & 63;
    const float4* wp = (const float4*)(We + j * 64 + h * 16);
    float4 w0 = wp[0], w1 = wp[1], w2 = wp[2], w3 = wp[3];
#pragma unroll 4
    for (int nl = 0; nl < 16; nl++) {
        const float* qr = &qs[nl][h * 16];
        float acc = w0.x * qr[0] + w0.y * qr[1] + w0.z * qr[2] + w0.w * qr[3]
                  + w1.x * qr[4] + w1.y * qr[5] + w1.z * qr[6] + w1.w * qr[7]
                  + w2.x * qr[8] + w2.y * qr[9] + w2.z * qr[10] + w2.w * qr[11]
                  + w3.x * qr[12] + w3.y * qr[13] + w3.z * qr[14] + w3.w * qr[15];
        g_p[(n0 + nl) * 256 + h * 64 + j] = acc;
    }
}

__global__ void k_chunksum() {
    __shared__ int sh[256];
    int b = blockIdx.x, t = threadIdx.x;
    int base = b * 1024;
    int sum = 0;
    for (int k = 0; k < 4; k++) {
        int i = base + k * 256 + t;
        if (i < N_NODES) sum += g_deg[i];
    }
    sh[t] = sum;
    __syncthreads();
    for (int off = 128; off; off >>= 1) {
        if (t < off) sh[t] += sh[t + off];
        __syncthreads();
    }
    if (t == 0) g_chunksum[b] = sh[0];
}

__global__ void k_scanmid() {
    int run = 0;
    for (int c = 0; c < NCHUNK; c++) {
        g_chunkoff[c] = run;
        run += g_chunksum[c];
    }
    g_rowptr[N_NODES] = run;
}

__global__ void k_scanchunk() {
    __shared__ int s[1024];
    int b = blockIdx.x, t = threadIdx.x;
    int i = b * 1024 + t;
    int v = (i < N_NODES) ? g_deg[i] : 0;
    s[t] = v;
    __syncthreads();
    for (int off = 1; off < 1024; off <<= 1) {
        int add = (t >= off) ? s[t - off] : 0;
        __syncthreads();
        s[t] += add;
        __syncthreads();
    }
    if (i < N_NODES) {
        int ex = g_chunkoff[b] + s[t] - v;   // exclusive prefix
        g_rowptr[i] = ex;
        g_cursor[i] = ex;
    }
}

__global__ void k_scatter() {
    int e = blockIdx.x * blockDim.x + threadIdx.x;
    if (e >= N_EDGES) return;
    int dst = g_dst[e];
    int p = atomicAdd(&g_cursor[dst], 1);
    g_csr_src[p] = g_src[e];
    g_csr_dst[p] = dst;
    g_csr_eid[p] = e;
}

// logits in CSR order: 64 CSR slots/block, thread = (el = t>>2, h = t&3).
#define EA_STRIDE 68
__global__ void k_logits(const float* __restrict__ ea) {
    __shared__ float eas[64 * EA_STRIDE];
    __shared__ int ss[64], sd[64], se[64];
    int e0 = blockIdx.x * 64, t = threadIdx.x;
    if (t < 64) {
        ss[t] = g_csr_src[e0 + t];
        sd[t] = g_csr_dst[e0 + t];
        se[t] = g_csr_eid[e0 + t];
    }
    __syncthreads();
    // stage ea rows (gathered by eid): 4 threads per row, 16 floats each
    {
        int row = t >> 2, part = t & 3;
        const float4* src4 = (const float4*)(ea + (size_t)se[row] * 64 + part * 16);
        float* dstp = &eas[row * EA_STRIDE + part * 16];
#pragma unroll
        for (int k = 0; k < 4; k++) {
            float4 v = src4[k];
            dstp[k * 4 + 0] = v.x;
            dstp[k * 4 + 1] = v.y;
            dstp[k * 4 + 2] = v.z;
            dstp[k * 4 + 3] = v.w;
        }
    }
    __syncthreads();
    int el = t >> 2, h = t & 3;
    int dst = sd[el], src = ss[el];
    const float4* qp = (const float4*)(g_q + dst * 64 + h * 16);
    const float4* kp = (const float4*)(g_k + src * 64 + h * 16);
    float acc = 0.0f;
#pragma unroll
    for (int c = 0; c < 4; c++) {
        float4 qv = qp[c], kv = kp[c];
        acc += qv.x * kv.x + qv.y * kv.y + qv.z * kv.z + qv.w * kv.w;
    }
    const float4* pp = (const float4*)(g_p + dst * 256 + h * 64);
    const float4* er = (const float4*)&eas[el * EA_STRIDE];
#pragma unroll
    for (int j = 0; j < 16; j++) {
        float4 pv = pp[j];
        float4 ev = er[j];
        acc += ev.x * pv.x + ev.y * pv.y + ev.z * pv.z + ev.w * pv.w;
    }
    float logit = acc * 0.25f;   // 1/sqrt(16)
    g_att[e0 * 4 + t] = logit;   // coalesced
    atomicMax(&g_menc[dst * 4 + h], fenc(logit));
}

__global__ void k_exp() {
    int i = blockIdx.x * blockDim.x + threadIdx.x;
    if (i >= N_EDGES * HEADS) return;
    int e = i >> 2, h = i & 3;
    int dst = g_csr_dst[e];
    float m = fdec(g_menc[dst * 4 + h]);
    float ex = __expf(g_att[i] - m);
    g_att[i] = ex;               // unnormalized; k_prop applies g_dinv
    atomicAdd(&g_denom[dst * 4 + h], ex);
}

__global__ void k_dinv() {
    int i = blockIdx.x * blockDim.x + threadIdx.x;
    if (i < N_NODES * HEADS) g_dinv[i] = 1.0f / (g_denom[i] + 1e-16f);
}

// propagation: warp per node, pure gather, 2-way unrolled for MLP.
// Normalization folded in via g_dinv; iter==7 fuses relu + residual.
__global__ void k_prop(int iter, const float* __restrict__ x, float* __restrict__ out) {
    int gid = blockIdx.x * blockDim.x + threadIdx.x;
    int node = gid >> 5;
    if (node >= N_NODES) return;
    int lane = gid & 31;
    const float* zold = (iter == 0) ? g_v : ((iter & 1) ? g_zA : g_zB);
    float* znew = (iter & 1) ? g_zB : g_zA;
    int beg = g_rowptr[node], end = g_rowptr[node + 1];
    int h = lane >> 3;
    float inv = g_dinv[node * 4 + h];
    float ax0 = 0.0f, ay0 = 0.0f, ax1 = 0.0f, ay1 = 0.0f;
    int i = beg;
    for (; i + 1 < end; i += 2) {
        int s0 = g_csr_src[i], s1 = g_csr_src[i + 1];
        float a0 = g_att[i * 4 + h];
        float a1 = g_att[(i + 1) * 4 + h];
        float2 z0 = *(const float2*)(zold + s0 * 64 + lane * 2);
        float2 z1 = *(const float2*)(zold + s1 * 64 + lane * 2);
        ax0 += a0 * z0.x; ay0 += a0 * z0.y;
        ax1 += a1 * z1.x; ay1 += a1 * z1.y;
    }
    if (i < end) {
        int s = g_csr_src[i];
        float a = g_att[i * 4 + h];
        float2 z = *(const float2*)(zold + s * 64 + lane * 2);
        ax0 += a * z.x; ay0 += a * z.y;
    }
    float ax = ax0 + ax1, ay = ay0 + ay1;
    float2 vv = *(const float2*)(g_v + node * 64 + lane * 2);
    float ox = 0.1f * vv.x + 0.9f * (ax * inv);
    float oy = 0.1f * vv.y + 0.9f * (ay * inv);
    if (iter == 7) {
        float2 xv = *(const float2*)(x + node * 64 + lane * 2);
        float2 o;
        o.x = xv.x + fmaxf(ox, 0.0f);
        o.y = xv.y + fmaxf(oy, 0.0f);
        *(float2*)(out + node * 64 + lane * 2) = o;
    } else {
        float2 o; o.x = ox; o.y = oy;
        *(float2*)(znew + node * 64 + lane * 2) = o;
    }
}

// ---------------- launch ----------------
// Launch #4 gets profiled by the harness's ncu slot -> keep k_qkv there to
// verify the f32x2 prediction.
extern "C" void kernel_launch(void* const* d_in, const int* in_sizes, int n_in,
                              void* d_out, int out_size) {
    const float*     x  = (const float*)d_in[0];
    const long long* ei = (const long long*)d_in[1];
    const float*     ea = (const float*)d_in[2];
    const float*     Wq = (const float*)d_in[3];
    const float*     Wk = (const float*)d_in[4];
    const float*     Wv = (const float*)d_in[5];
    const float*     We = (const float*)d_in[6];
    float* out = (float*)d_out;

    k_detect<<<1, 1>>>(ei);                                   // 1
    k_zero<<<(N_NODES * HEADS + 255) / 256, 256>>>();         // 2
    k_prep<<<(N_EDGES + 255) / 256, 256>>>(ei);               // 3
    k_qkv<<<N_NODES / 32, 256>>>(x, Wq, Wk, Wv);              // 4  <- profiled
    k_p<<<N_NODES / 16, 256>>>(We);                           // 5
    k_chunksum<<<NCHUNK, 256>>>();                            // 6
    k_scanmid<<<1, 1>>>();                                    // 7
    k_scanchunk<<<NCHUNK, 1024>>>();                          // 8
    k_scatter<<<(N_EDGES + 255) / 256, 256>>>();              // 9
    k_logits<<<N_EDGES / 64, 256>>>(ea);                      // 10
    k_exp<<<(N_EDGES * HEADS + 255) / 256, 256>>>();          // 11
    k_dinv<<<(N_NODES * HEADS + 255) / 256, 256>>>();         // 12
    for (int it = 0; it < 8; it++)
        k_prop<<<(N_NODES * 32 + 255) / 256, 256>>>(it, x, out);  // 13-20
}